// round 15
// baseline (speedup 1.0000x reference)
#include <cuda_runtime.h>
#include <cstdint>

#define NN 2048
#define BB 4
#define THREADS 128
#define ROWS_PER_BLOCK 8                         // 2 row-groups x 4 rows
#define BLOCKS_PER_BATCH (NN / ROWS_PER_BLOCK)   // 256
#define CHUNK 128                                // table chunk entries (=THREADS)
#define NCH 16                                   // chunks per batch
#define NWIN 32                                  // 16 chunks x 2 windows
#define NSTAGES 3
#define STAGE_BYTES 1024                         // 4 rows x 32 j x 4B x 2 arrays

typedef unsigned long long u64;

__device__ __forceinline__ void fma2(u64& d, u64 a, u64 b) {
    asm("fma.rn.f32x2 %0, %1, %2, %0;" : "+l"(d) : "l"(a), "l"(b));
}
__device__ __forceinline__ u64 pack2(float lo, float hi) {
    u64 r;
    asm("mov.b64 %0, {%1, %2};" : "=l"(r) : "f"(lo), "f"(hi));
    return r;
}
__device__ __forceinline__ void unpack2(float& lo, float& hi, u64 v) {
    asm("mov.b64 {%0, %1}, %2;" : "=f"(lo), "=f"(hi) : "l"(v));
}
__device__ __forceinline__ u64 add2(u64 a, u64 b) {
    u64 r;
    asm("add.rn.f32x2 %0, %1, %2;" : "=l"(r) : "l"(a), "l"(b));
    return r;
}
__device__ __forceinline__ void cp16(uint32_t dst_smem, const void* src) {
    asm volatile("cp.async.cg.shared.global [%0], [%1], 16;"
                 :: "r"(dst_smem), "l"(src));
}
#define CP_COMMIT() asm volatile("cp.async.commit_group;")
#define CP_WAIT2()  asm volatile("cp.async.wait_group 2;")

__global__ __launch_bounds__(THREADS, 7)
void kuramoto_kernel(const float* __restrict__ W,
                     const float* __restrict__ alpha,
                     const float4* __restrict__ theta,
                     const float4* __restrict__ gamma,
                     float4* __restrict__ out) {
    // Transformed table: u = c+s, v = s-c, nv = c-s  (double-buffered)
    __shared__ __align__(16) float4 u_tb[2][CHUNK];               // 4 KB
    __shared__ __align__(16) float4 v_tb[2][CHUNK];               // 4 KB
    __shared__ __align__(16) float4 nv_tb[2][CHUNK];              // 4 KB
    __shared__ __align__(16) char stage[4][NSTAGES][STAGE_BYTES]; // 12 KB
    __shared__ u64 red[4][4][4];                                  // [warp][r][4]

    const int b    = blockIdx.x / BLOCKS_PER_BATCH;
    const int row0 = (blockIdx.x % BLOCKS_PER_BATCH) * ROWS_PER_BLOCK;
    const int base = b * NN;

    const int tid    = threadIdx.x;
    const int warp   = tid >> 5;
    const int lane   = tid & 31;
    const int rowgrp = warp >> 1;             // rows 0-3 / 4-7
    const int jpart  = warp & 1;              // chunk j-half (64 j)
    const int i0     = row0 + rowgrp * 4;     // first of this warp's 4 rows

    const float* __restrict__ Wr = W     + (size_t)(base + i0) * NN;
    const float* __restrict__ Ar = alpha + (size_t)(base + i0) * NN;

    // W/alpha LDGSTS source: row = lane>>3, j-seg = 4*(lane&7)
    const size_t src_row_off = (size_t)(lane >> 3) * NN + 4 * (lane & 7);
    const uint32_t my_stage =
        (uint32_t)__cvta_generic_to_shared(&stage[warp][0][0]) + lane * 16;
    const char* stage_rd = &stage[warp][0][0];

    // window w: chunk = w>>1, within-chunk slice = jpart*64 + (w&1)*32
    #define GOFF(w) (((w) >> 1) * CHUNK + jpart * 64 + ((w) & 1) * 32)

    #define PREF_WIN(w) do {                                             \
        const uint32_t _dst = my_stage + ((w) % NSTAGES) * STAGE_BYTES;  \
        cp16(_dst,       Wr + src_row_off + GOFF(w));                    \
        cp16(_dst + 512, Ar + src_row_off + GOFF(w));                    \
    } while (0)

    // Build table entry `tid` of a chunk into buffer nb from register theta
    #define BUILD(nb, th) do {                                           \
        float4 _s, _c;                                                   \
        __sincosf((th).x, &_s.x, &_c.x);                                 \
        __sincosf((th).y, &_s.y, &_c.y);                                 \
        __sincosf((th).z, &_s.z, &_c.z);                                 \
        __sincosf((th).w, &_s.w, &_c.w);                                 \
        u_tb[nb][tid]  = make_float4(_c.x + _s.x, _c.y + _s.y,           \
                                     _c.z + _s.z, _c.w + _s.w);          \
        v_tb[nb][tid]  = make_float4(_s.x - _c.x, _s.y - _c.y,           \
                                     _s.z - _c.z, _s.w - _c.w);          \
        nv_tb[nb][tid] = make_float4(_c.x - _s.x, _c.y - _s.y,           \
                                     _c.z - _s.z, _c.w - _s.w);          \
    } while (0)

    // Accumulators: S = P+Q, D = P-Q, packed over d-pairs
    u64 S01[4], S23[4], D01[4], D23[4];
    #pragma unroll
    for (int r = 0; r < 4; ++r) { S01[r] = 0; S23[r] = 0; D01[r] = 0; D23[r] = 0; }

    // Prologue: build chunks 0,1; prefetch theta for chunk 2; prefetch win 0..2
    {
        const float4 th0 = theta[base + tid];
        const float4 th1 = theta[base + CHUNK + tid];
        BUILD(0, th0);
        BUILD(1, th1);
    }
    float4 th_reg = theta[base + 2 * CHUNK + tid];   // for chunk 2
    PREF_WIN(0); CP_COMMIT();
    PREF_WIN(1); CP_COMMIT();
    PREF_WIN(2); CP_COMMIT();
    __syncthreads();           // tables 0,1 visible block-wide

    for (int w = 0; w < NWIN; ++w) {
        const int ch = w >> 1;

        if ((w & 1) == 0 && w > 0) {
            __syncthreads();   // table ch visible; buffer (ch+1)&1 free
            // Overlapped build of chunk ch+1 from register theta, then
            // prefetch theta for chunk ch+2 (a full chunk of lead time).
            if (ch + 1 < NCH) BUILD((ch + 1) & 1, th_reg);
            if (ch + 2 < NCH) th_reg = theta[base + (ch + 2) * CHUNK + tid];
        }

        CP_WAIT2();            // window w's staged bytes ready (2 in flight)
        __syncwarp();          // intra-warp visibility

        // ---- compute window w ----
        const int jloc = jpart * 64 + (w & 1) * 32 + lane;   // chunk-local j
        const int buf  = ch & 1;
        const ulonglong2 up  = *reinterpret_cast<const ulonglong2*>(&u_tb[buf][jloc]);
        const ulonglong2 vp  = *reinterpret_cast<const ulonglong2*>(&v_tb[buf][jloc]);
        const ulonglong2 nvp = *reinterpret_cast<const ulonglong2*>(&nv_tb[buf][jloc]);
        const char* st = stage_rd + (w % NSTAGES) * STAGE_BYTES;

        #pragma unroll
        for (int r = 0; r < 4; ++r) {
            const float wv = *reinterpret_cast<const float*>(st + r * 128 + lane * 4);
            const float av = *reinterpret_cast<const float*>(st + 512 + r * 128 + lane * 4);
            float sa, ca;
            __sincosf(av, &sa, &ca);
            const float Av = wv * ca;            // W * cos(alpha)
            const float Bv = wv * sa;            // W * sin(alpha)
            const u64 Av2 = pack2(Av, Av);
            const u64 Bv2 = pack2(Bv, Bv);
            // S += Av*u + Bv*v ;  D += Bv*u + Av*nv   (only 2 splat-packs)
            fma2(S01[r], Av2, up.x);  fma2(S01[r], Bv2, vp.x);
            fma2(S23[r], Av2, up.y);  fma2(S23[r], Bv2, vp.y);
            fma2(D01[r], Bv2, up.x);  fma2(D01[r], Av2, nvp.x);
            fma2(D23[r], Bv2, up.y);  fma2(D23[r], Av2, nvp.y);
        }

        __syncwarp();          // all lanes done reading slot before overwrite
        if (w + NSTAGES < NWIN) PREF_WIN(w + NSTAGES);
        CP_COMMIT();           // one group per iteration
    }

    // Butterfly: reduce all 4 rows' packed sums across the 32 lanes
    #pragma unroll
    for (int off = 16; off > 0; off >>= 1) {
        #pragma unroll
        for (int r = 0; r < 4; ++r) {
            S01[r] = add2(S01[r], __shfl_xor_sync(0xffffffffu, S01[r], off));
            S23[r] = add2(S23[r], __shfl_xor_sync(0xffffffffu, S23[r], off));
            D01[r] = add2(D01[r], __shfl_xor_sync(0xffffffffu, D01[r], off));
            D23[r] = add2(D23[r], __shfl_xor_sync(0xffffffffu, D23[r], off));
        }
    }

    if (lane == 0) {
        #pragma unroll
        for (int r = 0; r < 4; ++r) {
            red[warp][r][0] = S01[r];  red[warp][r][1] = S23[r];
            red[warp][r][2] = D01[r];  red[warp][r][3] = D23[r];
        }
    }
    __syncthreads();

    // 8 threads: one output row each; combine the two j-half warps
    if (tid < ROWS_PER_BLOCK) {
        const int g = tid >> 2;              // row-group
        const int r = tid & 3;               // row within group
        const int i = row0 + g * 4 + r;

        const u64 s01 = add2(red[2 * g][r][0], red[2 * g + 1][r][0]);
        const u64 s23 = add2(red[2 * g][r][1], red[2 * g + 1][r][1]);
        const u64 d01 = add2(red[2 * g][r][2], red[2 * g + 1][r][2]);
        const u64 d23 = add2(red[2 * g][r][3], red[2 * g + 1][r][3]);

        float S0, S1, S2, S3, D0, D1, D2, D3;
        unpack2(S0, S1, s01); unpack2(S2, S3, s23);
        unpack2(D0, D1, d01); unpack2(D2, D3, d23);

        // P = (S+D)/2, Q = (S-D)/2; fold the 1/2 into the 1/N constant
        const float P0 = S0 + D0, Q0 = S0 - D0;
        const float P1 = S1 + D1, Q1 = S1 - D1;
        const float P2 = S2 + D2, Q2 = S2 - D2;
        const float P3 = S3 + D3, Q3 = S3 - D3;

        const float inv2n = 0.5f / (float)NN;    // COUPLING / (2N)
        const float4 g4 = gamma[base + i];
        const float4 th = theta[base + i];
        float4 si, ci;
        __sincosf(th.x, &si.x, &ci.x);
        __sincosf(th.y, &si.y, &ci.y);
        __sincosf(th.z, &si.z, &ci.z);
        __sincosf(th.w, &si.w, &ci.w);

        // theta_next = gamma + (1/N)(c_i*Q - s_i*P)   (theta cancels, DT=ATTR=1)
        float n0 = g4.x + inv2n * (ci.x * Q0 - si.x * P0);
        float n1 = g4.y + inv2n * (ci.y * Q1 - si.y * P1);
        float n2 = g4.z + inv2n * (ci.z * Q2 - si.z * P2);
        float n3 = g4.w + inv2n * (ci.w * Q3 - si.w * P3);

        float nrm = sqrtf(n0 * n0 + n1 * n1 + n2 * n2 + n3 * n3);
        float inv = 1.0f / fmaxf(nrm, 1e-6f);
        out[base + i] = make_float4(n0 * inv, n1 * inv, n2 * inv, n3 * inv);
    }
}

extern "C" void kernel_launch(void* const* d_in, const int* in_sizes, int n_in,
                              void* d_out, int out_size) {
    const float* theta = (const float*)d_in[0];   // [B, N, 4]
    const float* gamma = (const float*)d_in[1];   // [B, N, 4]
    const float* W     = (const float*)d_in[2];   // [B, N, N]
    const float* alpha = (const float*)d_in[3];   // [B, N, N]
    float* out = (float*)d_out;                   // [B, N, 4]

    // Single kernel: in-kernel double-buffered table built one chunk ahead
    // from register-prefetched theta (no pre-kernel, no boundary drain),
    // (u,v,-v) transform cuts one splat-pack per row-window, 7 CTAs/SM.
    kuramoto_kernel<<<BB * BLOCKS_PER_BATCH, THREADS>>>(
        W, alpha, (const float4*)theta, (const float4*)gamma, (float4*)out);
}

// round 16
// speedup vs baseline: 1.0126x; 1.0126x over previous
#include <cuda_runtime.h>
#include <cstdint>

#define NN 2048
#define BB 4
#define THREADS 128
#define ROWS_PER_BLOCK 8                         // 2 row-groups x 4 rows
#define BLOCKS_PER_BATCH (NN / ROWS_PER_BLOCK)   // 256
#define CHUNK 128                                // table chunk entries (=THREADS)
#define NCH 16                                   // chunks per batch
#define NWIN 32                                  // 16 chunks x 2 windows
#define NSTAGES 4                                // power-of-2 slots
#define STAGE_BYTES 1024                         // 4 rows x 32 j x 4B x 2 arrays

typedef unsigned long long u64;

__device__ __forceinline__ void fma2(u64& d, u64 a, u64 b) {
    asm("fma.rn.f32x2 %0, %1, %2, %0;" : "+l"(d) : "l"(a), "l"(b));
}
__device__ __forceinline__ u64 pack2(float lo, float hi) {
    u64 r;
    asm("mov.b64 %0, {%1, %2};" : "=l"(r) : "f"(lo), "f"(hi));
    return r;
}
__device__ __forceinline__ void unpack2(float& lo, float& hi, u64 v) {
    asm("mov.b64 {%0, %1}, %2;" : "=f"(lo), "=f"(hi) : "l"(v));
}
__device__ __forceinline__ u64 add2(u64 a, u64 b) {
    u64 r;
    asm("add.rn.f32x2 %0, %1, %2;" : "=l"(r) : "l"(a), "l"(b));
    return r;
}
__device__ __forceinline__ void cp16(uint32_t dst_smem, const void* src) {
    asm volatile("cp.async.cg.shared.global [%0], [%1], 16;"
                 :: "r"(dst_smem), "l"(src));
}
#define CP_COMMIT() asm volatile("cp.async.commit_group;")
#define CP_WAIT3()  asm volatile("cp.async.wait_group 3;")

__global__ __launch_bounds__(THREADS, 7)
void kuramoto_kernel(const float* __restrict__ W,
                     const float* __restrict__ alpha,
                     const float4* __restrict__ theta,
                     const float4* __restrict__ gamma,
                     float4* __restrict__ out) {
    // Transformed table: u = c+s, v = s-c, nv = c-s  (double-buffered)
    __shared__ __align__(16) float4 u_tb[2][CHUNK];               // 4 KB
    __shared__ __align__(16) float4 v_tb[2][CHUNK];               // 4 KB
    __shared__ __align__(16) float4 nv_tb[2][CHUNK];              // 4 KB
    __shared__ __align__(16) char stage[4][NSTAGES][STAGE_BYTES]; // 16 KB
    __shared__ u64 red[4][4][4];                                  // [warp][r][4]

    const int b    = blockIdx.x / BLOCKS_PER_BATCH;
    const int row0 = (blockIdx.x % BLOCKS_PER_BATCH) * ROWS_PER_BLOCK;
    const int base = b * NN;

    const int tid    = threadIdx.x;
    const int warp   = tid >> 5;
    const int lane   = tid & 31;
    const int rowgrp = warp >> 1;             // rows 0-3 / 4-7
    const int jpart  = warp & 1;              // chunk j-half (64 j)
    const int i0     = row0 + rowgrp * 4;     // first of this warp's 4 rows

    const float* __restrict__ Wr = W     + (size_t)(base + i0) * NN;
    const float* __restrict__ Ar = alpha + (size_t)(base + i0) * NN;

    // W/alpha LDGSTS source: row = lane>>3, j-seg = 4*(lane&7)
    const size_t src_row_off = (size_t)(lane >> 3) * NN + 4 * (lane & 7);
    const uint32_t my_stage =
        (uint32_t)__cvta_generic_to_shared(&stage[warp][0][0]) + lane * 16;
    const char* stage_rd = &stage[warp][0][0];
    const int jp64 = jpart * 64 + lane;       // hoisted j addressing

    // window w: chunk = w>>1, slice = jpart*64 + (w&1)*32
    #define GOFF(w) (((w) >> 1) * CHUNK + jpart * 64 + ((w) & 1) * 32)

    #define PREF_WIN(w) do {                                             \
        const uint32_t _dst = my_stage + ((w) & 3) * STAGE_BYTES;        \
        cp16(_dst,       Wr + src_row_off + GOFF(w));                    \
        cp16(_dst + 512, Ar + src_row_off + GOFF(w));                    \
    } while (0)

    // Build table entry `tid` of a chunk into buffer nb from register theta
    #define BUILD(nb, th) do {                                           \
        float4 _s, _c;                                                   \
        __sincosf((th).x, &_s.x, &_c.x);                                 \
        __sincosf((th).y, &_s.y, &_c.y);                                 \
        __sincosf((th).z, &_s.z, &_c.z);                                 \
        __sincosf((th).w, &_s.w, &_c.w);                                 \
        u_tb[nb][tid]  = make_float4(_c.x + _s.x, _c.y + _s.y,           \
                                     _c.z + _s.z, _c.w + _s.w);          \
        v_tb[nb][tid]  = make_float4(_s.x - _c.x, _s.y - _c.y,           \
                                     _s.z - _c.z, _s.w - _c.w);          \
        nv_tb[nb][tid] = make_float4(_c.x - _s.x, _c.y - _s.y,           \
                                     _c.z - _s.z, _c.w - _s.w);          \
    } while (0)

    // Accumulators: S = P+Q, D = P-Q, packed over d-pairs
    u64 S01[4], S23[4], D01[4], D23[4];
    #pragma unroll
    for (int r = 0; r < 4; ++r) { S01[r] = 0; S23[r] = 0; D01[r] = 0; D23[r] = 0; }

    // Prologue: build chunks 0,1; prefetch theta for chunk 2; prefetch win 0..3
    {
        const float4 th0 = theta[base + tid];
        const float4 th1 = theta[base + CHUNK + tid];
        BUILD(0, th0);
        BUILD(1, th1);
    }
    float4 th_reg = theta[base + 2 * CHUNK + tid];   // for chunk 2
    PREF_WIN(0); CP_COMMIT();
    PREF_WIN(1); CP_COMMIT();
    PREF_WIN(2); CP_COMMIT();
    PREF_WIN(3); CP_COMMIT();
    __syncthreads();           // tables 0,1 visible block-wide

    for (int ch = 0; ch < NCH; ++ch) {
        if (ch > 0) {
            __syncthreads();   // table ch visible; buffer (ch+1)&1 free
            if (ch + 1 < NCH) BUILD((ch + 1) & 1, th_reg);
            if (ch + 2 < NCH) th_reg = theta[base + (ch + 2) * CHUNK + tid];
        }
        const int buf = ch & 1;

        #pragma unroll
        for (int k = 0; k < 2; ++k) {
            const int w = 2 * ch + k;

            // Table LDS hoisted above the pipeline wait (latency in shadow)
            const int jloc = jp64 + k * 32;   // chunk-local j
            const ulonglong2 up  = *reinterpret_cast<const ulonglong2*>(&u_tb[buf][jloc]);
            const ulonglong2 vp  = *reinterpret_cast<const ulonglong2*>(&v_tb[buf][jloc]);
            const ulonglong2 nvp = *reinterpret_cast<const ulonglong2*>(&nv_tb[buf][jloc]);

            CP_WAIT3();        // window w's staged bytes ready (3 in flight)
            __syncwarp();      // intra-warp visibility

            // Static slot: (2ch+k)&3 = 2*(ch&1)+k
            const char* st = stage_rd + (2 * buf + k) * STAGE_BYTES;

            #pragma unroll
            for (int r = 0; r < 4; ++r) {
                const float wv = *reinterpret_cast<const float*>(st + r * 128 + lane * 4);
                const float av = *reinterpret_cast<const float*>(st + 512 + r * 128 + lane * 4);
                float sa, ca;
                __sincosf(av, &sa, &ca);
                const float Av = wv * ca;        // W * cos(alpha)
                const float Bv = wv * sa;        // W * sin(alpha)
                const u64 Av2 = pack2(Av, Av);
                const u64 Bv2 = pack2(Bv, Bv);
                // S += Av*u + Bv*v ;  D += Bv*u + Av*nv   (only 2 splat-packs)
                fma2(S01[r], Av2, up.x);  fma2(S01[r], Bv2, vp.x);
                fma2(S23[r], Av2, up.y);  fma2(S23[r], Bv2, vp.y);
                fma2(D01[r], Bv2, up.x);  fma2(D01[r], Av2, nvp.x);
                fma2(D23[r], Bv2, up.y);  fma2(D23[r], Av2, nvp.y);
            }

            __syncwarp();      // all lanes done reading slot before overwrite
            if (w + NSTAGES < NWIN) PREF_WIN(w + NSTAGES);
            CP_COMMIT();       // one group per window
        }
    }

    // Butterfly: reduce all 4 rows' packed sums across the 32 lanes
    #pragma unroll
    for (int off = 16; off > 0; off >>= 1) {
        #pragma unroll
        for (int r = 0; r < 4; ++r) {
            S01[r] = add2(S01[r], __shfl_xor_sync(0xffffffffu, S01[r], off));
            S23[r] = add2(S23[r], __shfl_xor_sync(0xffffffffu, S23[r], off));
            D01[r] = add2(D01[r], __shfl_xor_sync(0xffffffffu, D01[r], off));
            D23[r] = add2(D23[r], __shfl_xor_sync(0xffffffffu, D23[r], off));
        }
    }

    if (lane == 0) {
        #pragma unroll
        for (int r = 0; r < 4; ++r) {
            red[warp][r][0] = S01[r];  red[warp][r][1] = S23[r];
            red[warp][r][2] = D01[r];  red[warp][r][3] = D23[r];
        }
    }
    __syncthreads();

    // 8 threads: one output row each; combine the two j-half warps
    if (tid < ROWS_PER_BLOCK) {
        const int g = tid >> 2;              // row-group
        const int r = tid & 3;               // row within group
        const int i = row0 + g * 4 + r;

        const u64 s01 = add2(red[2 * g][r][0], red[2 * g + 1][r][0]);
        const u64 s23 = add2(red[2 * g][r][1], red[2 * g + 1][r][1]);
        const u64 d01 = add2(red[2 * g][r][2], red[2 * g + 1][r][2]);
        const u64 d23 = add2(red[2 * g][r][3], red[2 * g + 1][r][3]);

        float S0, S1, S2, S3, D0, D1, D2, D3;
        unpack2(S0, S1, s01); unpack2(S2, S3, s23);
        unpack2(D0, D1, d01); unpack2(D2, D3, d23);

        // P = (S+D)/2, Q = (S-D)/2; fold the 1/2 into the 1/N constant
        const float P0 = S0 + D0, Q0 = S0 - D0;
        const float P1 = S1 + D1, Q1 = S1 - D1;
        const float P2 = S2 + D2, Q2 = S2 - D2;
        const float P3 = S3 + D3, Q3 = S3 - D3;

        const float inv2n = 0.5f / (float)NN;    // COUPLING / (2N)
        const float4 g4 = gamma[base + i];
        const float4 th = theta[base + i];
        float4 si, ci;
        __sincosf(th.x, &si.x, &ci.x);
        __sincosf(th.y, &si.y, &ci.y);
        __sincosf(th.z, &si.z, &ci.z);
        __sincosf(th.w, &si.w, &ci.w);

        // theta_next = gamma + (1/N)(c_i*Q - s_i*P)   (theta cancels, DT=ATTR=1)
        float n0 = g4.x + inv2n * (ci.x * Q0 - si.x * P0);
        float n1 = g4.y + inv2n * (ci.y * Q1 - si.y * P1);
        float n2 = g4.z + inv2n * (ci.z * Q2 - si.z * P2);
        float n3 = g4.w + inv2n * (ci.w * Q3 - si.w * P3);

        float nrm = sqrtf(n0 * n0 + n1 * n1 + n2 * n2 + n3 * n3);
        float inv = 1.0f / fmaxf(nrm, 1e-6f);
        out[base + i] = make_float4(n0 * inv, n1 * inv, n2 * inv, n3 * inv);
    }
}

extern "C" void kernel_launch(void* const* d_in, const int* in_sizes, int n_in,
                              void* d_out, int out_size) {
    const float* theta = (const float*)d_in[0];   // [B, N, 4]
    const float* gamma = (const float*)d_in[1];   // [B, N, 4]
    const float* W     = (const float*)d_in[2];   // [B, N, N]
    const float* alpha = (const float*)d_in[3];   // [B, N, N]
    float* out = (float*)d_out;                   // [B, N, 4]

    // Single kernel, issue-slimmed: chunk-nested loop with static window
    // unroll, power-of-2 slots (NSTAGES=4), table LDS hoisted into the
    // pipeline-wait shadow, in-kernel double-buffered (u,v,-v) table.
    kuramoto_kernel<<<BB * BLOCKS_PER_BATCH, THREADS>>>(
        W, alpha, (const float4*)theta, (const float4*)gamma, (float4*)out);
}